// round 2
// baseline (speedup 1.0000x reference)
#include <cuda_runtime.h>
#include <cstdint>

// Spatial correlation sampler: out[b, dh*9+dw, h, w] =
//   (1/C) * sum_c in1[b,c,h,w] * in2[b,c,h+dh-4,w+dw-4]   (zero-padded)
// B=8, C=256, H=128, W=256, patch=9.
//
// R2: 8 w-px per thread + packed fma.rn.f32x2.
// Block = 9 warps (one per dh), warp = 8 hh x 4 wgroups. Tile 8h x 32w.

#define BB   8
#define CC_  256
#define HH   128
#define WW   256
#define RAD  4
#define PATCH 9

#define TH   8
#define TW   32
#define CCH  4                       // channels per stage
#define ROWS2 (TH + 2*RAD)           // 16 in2 rows
#define P2   44                      // in2 row pitch (floats), 40 used
#define P1   36                      // in1 row pitch (floats), 32 used
#define IN2F (ROWS2 * P2)            // 704
#define CHF  (IN2F + TH * P1)        // 992 floats per channel
#define STAGEF (CCH * CHF)           // 3968 floats per stage
#define IN2_CH_CHUNKS (ROWS2 * 10)   // 160 (10 chunks of 4 floats cover 40)
#define IN1_CH_CHUNKS (TH * 8)       // 64
#define CH_CHUNKS (IN2_CH_CHUNKS + IN1_CH_CHUNKS)  // 224
#define TOT_CHUNKS (CCH * CH_CHUNKS) // 896
#define NTHREADS 288

__device__ __forceinline__ unsigned smem_u32(const void* p) {
    return (unsigned)__cvta_generic_to_shared(p);
}
__device__ __forceinline__ void cp16(unsigned dst, const void* src, int src_bytes) {
    asm volatile("cp.async.cg.shared.global [%0], [%1], 16, %2;\n"
                 :: "r"(dst), "l"(src), "r"(src_bytes));
}
__device__ __forceinline__ unsigned long long pk(float lo, float hi) {
    unsigned long long v;
    asm("mov.b64 %0, {%1, %2};" : "=l"(v) : "f"(lo), "f"(hi));
    return v;
}
__device__ __forceinline__ void fma2(unsigned long long& d,
                                     unsigned long long a, unsigned long long b) {
    asm("fma.rn.f32x2 %0, %1, %2, %3;" : "=l"(d) : "l"(a), "l"(b), "l"(d));
}
__device__ __forceinline__ void upk(float& lo, float& hi, unsigned long long v) {
    asm("mov.b64 {%0, %1}, %2;" : "=f"(lo), "=f"(hi) : "l"(v));
}

__global__ void __launch_bounds__(NTHREADS, 1)
corr_kernel(const float* __restrict__ in1,
            const float* __restrict__ in2,
            float* __restrict__ out)
{
    __shared__ __align__(16) float sm[2 * STAGEF];

    const int tid  = threadIdx.x;
    const int lane = tid & 31;
    const int dh   = tid >> 5;        // warp id = displacement row 0..8
    const int wg   = lane & 3;        // 4 wgroups x 8 px = 32 w
    const int hh   = lane >> 2;       // 8 rows

    const int w0 = blockIdx.x * TW;
    const int h0 = blockIdx.y * TH;
    const int b  = blockIdx.z;

    const float* __restrict__ in1b = in1 + (size_t)b * CC_ * HH * WW;
    const float* __restrict__ in2b = in2 + (size_t)b * CC_ * HH * WW;

    unsigned long long acc[PATCH][4];
#pragma unroll
    for (int dw = 0; dw < PATCH; dw++)
#pragma unroll
        for (int j = 0; j < 4; j++) acc[dw][j] = 0ull;

    const int off_win = (hh + dh) * P2 + wg * 8;       // in2 window start (floats)
    const int off_a   = IN2F + hh * P1 + wg * 8;       // in1 start

    // ---- stage loader ----
    auto load_stage = [&](int s) {
        float* buf = sm + (s & 1) * STAGEF;
        const int c0 = s * CCH;
#pragma unroll
        for (int it = 0; it < 4; it++) {
            int i = tid + it * NTHREADS;
            if (i >= TOT_CHUNKS) break;
            int ch = i / CH_CHUNKS;
            int r  = i - ch * CH_CHUNKS;
            const int c = c0 + ch;
            unsigned dst;
            const float* src;
            int sz = 16;
            if (r < IN2_CH_CHUNKS) {
                int row = r / 10;
                int ck  = r - row * 10;
                int gh = h0 - RAD + row;
                int gw = w0 - RAD + ck * 4;
                dst = smem_u32(buf + ch * CHF + row * P2 + ck * 4);
                if (gh < 0 || gh >= HH || gw < 0 || gw > WW - 4) {
                    sz = 0; src = in2b;               // full-chunk zero fill
                } else {
                    src = in2b + ((size_t)c * HH + gh) * WW + gw;
                }
            } else {
                int r2 = r - IN2_CH_CHUNKS;
                int row = r2 >> 3;
                int ck  = r2 & 7;
                src = in1b + ((size_t)c * HH + (h0 + row)) * WW + (w0 + ck * 4);
                dst = smem_u32(buf + ch * CHF + IN2F + row * P1 + ck * 4);
            }
            cp16(dst, src, sz);
        }
    };

    // ---- compute one resident stage ----
    auto compute_stage = [&](int s) {
        const float* buf = sm + (s & 1) * STAGEF;
#pragma unroll
        for (int cc = 0; cc < CCH; cc++) {
            const float* chp = buf + cc * CHF;
            const float4* wp = (const float4*)(chp + off_win);
            float4 q0 = wp[0], q1 = wp[1], q2 = wp[2], q3 = wp[3];
            const float4* ap4 = (const float4*)(chp + off_a);
            float4 a0 = ap4[0], a1 = ap4[1];

            // packed even pairs (win[2k], win[2k+1]) and odd pairs (win[2k+1], win[2k+2])
            unsigned long long pe[8], po[7], ap[4];
            pe[0] = pk(q0.x, q0.y); pe[1] = pk(q0.z, q0.w);
            pe[2] = pk(q1.x, q1.y); pe[3] = pk(q1.z, q1.w);
            pe[4] = pk(q2.x, q2.y); pe[5] = pk(q2.z, q2.w);
            pe[6] = pk(q3.x, q3.y); pe[7] = pk(q3.z, q3.w);
            po[0] = pk(q0.y, q0.z); po[1] = pk(q0.w, q1.x);
            po[2] = pk(q1.y, q1.z); po[3] = pk(q1.w, q2.x);
            po[4] = pk(q2.y, q2.z); po[5] = pk(q2.w, q3.x);
            po[6] = pk(q3.y, q3.z);
            ap[0] = pk(a0.x, a0.y); ap[1] = pk(a0.z, a0.w);
            ap[2] = pk(a1.x, a1.y); ap[3] = pk(a1.z, a1.w);

#pragma unroll
            for (int k = 0; k < 5; k++) {       // even dw = 2k
#pragma unroll
                for (int j = 0; j < 4; j++)
                    fma2(acc[2 * k][j], ap[j], pe[k + j]);
            }
#pragma unroll
            for (int k = 0; k < 4; k++) {       // odd dw = 2k+1
#pragma unroll
                for (int j = 0; j < 4; j++)
                    fma2(acc[2 * k + 1][j], ap[j], po[k + j]);
            }
        }
    };

    const int NST = CC_ / CCH;  // 64 stages

    load_stage(0);
    asm volatile("cp.async.commit_group;\n");

    for (int s = 0; s < NST; s++) {
        if (s + 1 < NST) {
            load_stage(s + 1);
            asm volatile("cp.async.commit_group;\n");
            asm volatile("cp.async.wait_group 1;\n");
        } else {
            asm volatile("cp.async.wait_group 0;\n");
        }
        __syncthreads();
        compute_stage(s);
        __syncthreads();
    }

    // ---- epilogue: 2 float4 stores per dw ----
    const float scale = 1.0f / (float)CC_;
    float* outp = out + (((size_t)b * (PATCH * PATCH) + dh * PATCH) * HH + (h0 + hh)) * WW
                      + (w0 + wg * 8);
#pragma unroll
    for (int dw = 0; dw < PATCH; dw++) {
        float l0, h0_, l1, h1_, l2, h2_, l3, h3_;
        upk(l0, h0_, acc[dw][0]);
        upk(l1, h1_, acc[dw][1]);
        upk(l2, h2_, acc[dw][2]);
        upk(l3, h3_, acc[dw][3]);
        float4 v0 = make_float4(l0 * scale, h0_ * scale, l1 * scale, h1_ * scale);
        float4 v1 = make_float4(l2 * scale, h2_ * scale, l3 * scale, h3_ * scale);
        float* p = outp + (size_t)dw * HH * WW;
        *(float4*)p = v0;
        *(float4*)(p + 4) = v1;
    }
}

extern "C" void kernel_launch(void* const* d_in, const int* in_sizes, int n_in,
                              void* d_out, int out_size)
{
    const float* in1 = (const float*)d_in[0];
    const float* in2 = (const float*)d_in[1];
    float* out = (float*)d_out;

    dim3 grid(WW / TW, HH / TH, BB);   // 8 x 16 x 8 = 1024 blocks
    dim3 block(NTHREADS);
    corr_kernel<<<grid, block>>>(in1, in2, out);
}